// round 4
// baseline (speedup 1.0000x reference)
#include <cuda_runtime.h>

#define GRID_G   152
#define GG       (152 * 152)          // 23104
#define NA       3
#define NCH      10                   // 7 + 3 classes
#define NB       64
#define NPOS     (NB * NA * GG)       // 4,435,968 = 17328 * 256 exactly
#define STRIDE_F 4.0f                 // 608 / 152
#define TPB      256
#define WARPS    (TPB / 32)
#define WROW     (32 * NCH)           // 320 floats staged per warp

__device__ __forceinline__ float fast_sigmoid(float v) {
    return 1.0f / (1.0f + __expf(-v));
}

__global__ void __launch_bounds__(TPB)
yolo_layer_kernel(const float* __restrict__ x, float* __restrict__ out)
{
    __shared__ float sb[TPB * NCH];   // 10240 B, partitioned per warp

    const int t    = threadIdx.x;
    const int w    = t >> 5;
    const int lane = t & 31;
    const int idx  = blockIdx.x * TPB + t;   // NPOS % TPB == 0

    const int s  = idx % GG;      // gy*G + gx
    const int ba = idx / GG;      // b*NA + a
    const int a  = ba % NA;

    const int gx = s % GRID_G;
    const int gy = s / GRID_G;

    // input: x[ba][c][s], c-stride = GG; coalesced across lanes, MLP=10
    const float* __restrict__ p = x + (size_t)ba * (NCH * GG) + s;

    const float v0 = __ldcs(p + 0 * GG);
    const float v1 = __ldcs(p + 1 * GG);
    const float v2 = __ldcs(p + 2 * GG);
    const float v3 = __ldcs(p + 3 * GG);
    const float v4 = __ldcs(p + 4 * GG);
    const float v5 = __ldcs(p + 5 * GG);
    const float v6 = __ldcs(p + 6 * GG);
    const float v7 = __ldcs(p + 7 * GG);
    const float v8 = __ldcs(p + 8 * GG);
    const float v9 = __ldcs(p + 9 * GG);

    // anchors folded: (anchor/stride)*stride = anchor
    const float aw = (a == 0) ? 11.0f : (a == 1) ? 24.0f : 42.0f;
    const float ah = (a == 0) ? 14.0f : (a == 1) ? 17.0f : 27.0f;

    float* __restrict__ row = sb + w * WROW + lane * NCH;
    row[0] = (fast_sigmoid(v0) + (float)gx) * STRIDE_F;
    row[1] = (fast_sigmoid(v1) + (float)gy) * STRIDE_F;
    row[2] = __expf(v2) * aw;
    row[3] = __expf(v3) * ah;
    row[4] = v4;
    row[5] = v5;
    row[6] = fast_sigmoid(v6);
    row[7] = fast_sigmoid(v7);
    row[8] = fast_sigmoid(v8);
    row[9] = fast_sigmoid(v9);

    __syncwarp();

    // Per-warp coalesced streaming copy: 320 floats = 80 float4.
    // lanes 0..31 copy f4[lane], f4[lane+32]; lanes 0..15 also f4[lane+64].
    const float4* __restrict__ s4 = (const float4*)(sb + w * WROW);
    float4* __restrict__ o4 =
        (float4*)(out + ((size_t)blockIdx.x * TPB + w * 32) * NCH);

    __stcs(&o4[lane],      s4[lane]);
    __stcs(&o4[lane + 32], s4[lane + 32]);
    if (lane < 16)
        __stcs(&o4[lane + 64], s4[lane + 64]);
}

extern "C" void kernel_launch(void* const* d_in, const int* in_sizes, int n_in,
                              void* d_out, int out_size)
{
    const float* x = (const float*)d_in[0];
    float* out = (float*)d_out;

    const int blocks = NPOS / TPB;   // 17328
    yolo_layer_kernel<<<blocks, TPB>>>(x, out);
}

// round 5
// speedup vs baseline: 1.0413x; 1.0413x over previous
#include <cuda_runtime.h>

#define GRID_G   152
#define GG       (152 * 152)          // 23104
#define NA       3
#define NCH      10                   // 7 + 3 classes
#define NB       64
#define NPOS     (NB * NA * GG)       // 4,435,968 = 17328 * 256 exactly
#define STRIDE_F 4.0f                 // 608 / 152
#define TPB      256
#define WROW     (32 * NCH)           // 320 floats staged per warp

__device__ __forceinline__ float fast_sigmoid(float v) {
    return 1.0f / (1.0f + __expf(-v));
}

__global__ void __launch_bounds__(TPB)
yolo_layer_kernel(const float* __restrict__ x, float* __restrict__ out)
{
    __shared__ float sb[TPB * NCH];   // 10240 B, partitioned per warp

    const int t    = threadIdx.x;
    const int w    = t >> 5;
    const int lane = t & 31;
    const int idx  = blockIdx.x * TPB + t;   // NPOS % TPB == 0

    const int s  = idx % GG;      // gy*G + gx
    const int ba = idx / GG;      // b*NA + a
    const int a  = ba % NA;

    const int gx = s % GRID_G;
    const int gy = s / GRID_G;

    // input: x[ba][c][s], c-stride = GG; coalesced across lanes, MLP=10
    const float* __restrict__ p = x + (size_t)ba * (NCH * GG) + s;

    const float v0 = p[0 * GG];
    const float v1 = p[1 * GG];
    const float v2 = p[2 * GG];
    const float v3 = p[3 * GG];
    const float v4 = p[4 * GG];
    const float v5 = p[5 * GG];
    const float v6 = p[6 * GG];
    const float v7 = p[7 * GG];
    const float v8 = p[8 * GG];
    const float v9 = p[9 * GG];

    // anchors folded: (anchor/stride)*stride = anchor
    const float aw = (a == 0) ? 11.0f : (a == 1) ? 24.0f : 42.0f;
    const float ah = (a == 0) ? 14.0f : (a == 1) ? 17.0f : 27.0f;

    float* __restrict__ row = sb + w * WROW + lane * NCH;
    row[0] = (fast_sigmoid(v0) + (float)gx) * STRIDE_F;
    row[1] = (fast_sigmoid(v1) + (float)gy) * STRIDE_F;
    row[2] = __expf(v2) * aw;
    row[3] = __expf(v3) * ah;
    row[4] = v4;
    row[5] = v5;
    row[6] = fast_sigmoid(v6);
    row[7] = fast_sigmoid(v7);
    row[8] = fast_sigmoid(v8);
    row[9] = fast_sigmoid(v9);

    __syncwarp();

    // Per-warp coalesced copy: 320 floats = 80 float4.
    // lanes 0..31 copy f4[lane], f4[lane+32]; lanes 0..15 also f4[lane+64].
    const float4* __restrict__ s4 = (const float4*)(sb + w * WROW);
    float4* __restrict__ o4 =
        (float4*)(out + ((size_t)blockIdx.x * TPB + w * 32) * NCH);

    o4[lane]      = s4[lane];
    o4[lane + 32] = s4[lane + 32];
    if (lane < 16)
        o4[lane + 64] = s4[lane + 64];
}

extern "C" void kernel_launch(void* const* d_in, const int* in_sizes, int n_in,
                              void* d_out, int out_size)
{
    const float* x = (const float*)d_in[0];
    float* out = (float*)d_out;

    const int blocks = NPOS / TPB;   // 17328
    yolo_layer_kernel<<<blocks, TPB>>>(x, out);
}

// round 6
// speedup vs baseline: 1.0425x; 1.0011x over previous
#include <cuda_runtime.h>
#include <cstdint>

#define GRID_G   152
#define GG       (152 * 152)          // 23104
#define NA       3
#define NCH      10                   // 7 + 3 classes
#define NB       64
#define NPOS     (NB * NA * GG)       // 4,435,968 = 17328 * 256 exactly
#define STRIDE_F 4.0f                 // 608 / 152
#define TPB      256
#define TILE_BYTES (TPB * NCH * 4)    // 10240 B per block

__device__ __forceinline__ float fast_sigmoid(float v) {
    return 1.0f / (1.0f + __expf(-v));
}

__device__ __forceinline__ uint32_t smem_u32(const void* p) {
    uint32_t a;
    asm("{ .reg .u64 t; cvta.to.shared.u64 t, %1; cvt.u32.u64 %0, t; }"
        : "=r"(a) : "l"(p));
    return a;
}

__global__ void __launch_bounds__(TPB)
yolo_layer_kernel(const float* __restrict__ x, float* __restrict__ out)
{
    __shared__ __align__(16) float sb[TPB * NCH];   // 10240 B = block's output tile

    const int t   = threadIdx.x;
    const int idx = blockIdx.x * TPB + t;   // NPOS % TPB == 0

    const int s  = idx % GG;      // gy*G + gx
    const int ba = idx / GG;      // b*NA + a
    const int a  = ba % NA;

    const int gx = s % GRID_G;
    const int gy = s / GRID_G;

    // input: x[ba][c][s], c-stride = GG; coalesced across lanes, MLP=10
    const float* __restrict__ p = x + (size_t)ba * (NCH * GG) + s;

    const float v0 = p[0 * GG];
    const float v1 = p[1 * GG];
    const float v2 = p[2 * GG];
    const float v3 = p[3 * GG];
    const float v4 = p[4 * GG];
    const float v5 = p[5 * GG];
    const float v6 = p[6 * GG];
    const float v7 = p[7 * GG];
    const float v8 = p[8 * GG];
    const float v9 = p[9 * GG];

    // anchors folded: (anchor/stride)*stride = anchor
    const float aw = (a == 0) ? 11.0f : (a == 1) ? 24.0f : 42.0f;
    const float ah = (a == 0) ? 14.0f : (a == 1) ? 17.0f : 27.0f;

    float* __restrict__ row = sb + t * NCH;
    row[0] = (fast_sigmoid(v0) + (float)gx) * STRIDE_F;
    row[1] = (fast_sigmoid(v1) + (float)gy) * STRIDE_F;
    row[2] = __expf(v2) * aw;
    row[3] = __expf(v3) * ah;
    row[4] = v4;
    row[5] = v5;
    row[6] = fast_sigmoid(v6);
    row[7] = fast_sigmoid(v7);
    row[8] = fast_sigmoid(v8);
    row[9] = fast_sigmoid(v9);

    __syncthreads();

    // Single bulk TMA store: SMEM tile -> contiguous 10240B output region.
    if (t == 0) {
        asm volatile("fence.proxy.async.shared::cta;" ::: "memory");
        float* gdst = out + (size_t)blockIdx.x * (TPB * NCH);
        const uint32_t saddr = smem_u32(sb);
        asm volatile(
            "cp.async.bulk.global.shared::cta.bulk_group [%0], [%1], %2;"
            :: "l"(gdst), "r"(saddr), "r"((uint32_t)TILE_BYTES)
            : "memory");
        asm volatile("cp.async.bulk.commit_group;" ::: "memory");
        asm volatile("cp.async.bulk.wait_group 0;" ::: "memory");
    }
}

extern "C" void kernel_launch(void* const* d_in, const int* in_sizes, int n_in,
                              void* d_out, int out_size)
{
    const float* x = (const float*)d_in[0];
    float* out = (float*)d_out;

    const int blocks = NPOS / TPB;   // 17328
    yolo_layer_kernel<<<blocks, TPB>>>(x, out);
}